// round 12
// baseline (speedup 1.0000x reference)
#include <cuda_runtime.h>

#define NN 131072
#define EE 1048576
#define GG 4096
#define SS 64
#define HH 128
#define CAP 128
#define NEG 0.2f
#define FULL 0xffffffffu
#define TGPB 16  // graphs per block in fused tail

// scratch (no allocs allowed). Zero-initialized at module load; fused_tail
// re-zeroes d_cnt after consuming it, so every graph replay starts from zeros.
__device__ int d_cnt[2][GG];
__device__ int d_srcbuf[2][GG * CAP];

// ---- filter: keep only edges whose dst is the self node (32g+31), 8 edges/thread ----
__global__ void filter_edges_kernel(const void* __restrict__ up_e,
                                    const void* __restrict__ down_e) {
    __shared__ int s_is32;
    const int tid = threadIdx.x;

    // per-block dtype detect: int64 buffers have zero high-words at odd ints.
    if (tid == 0) s_is32 = 0;
    __syncthreads();
    if (tid < 64) {
        int v = ((const int*)up_e)[2 * tid + 1];
        if (v != 0) s_is32 = 1;          // benign same-value race
    }
    __syncthreads();
    const int is32 = s_is32;

    const long long Q = EE / 8;
    long long i8 = (long long)blockIdx.x * blockDim.x + tid;
    int b = 0;
    const void* ep = up_e;
    if (i8 >= Q) { b = 1; ep = down_e; i8 -= Q; }

    int dst[8];
    if (is32) {
        const int4* dp = (const int4*)((const int*)ep + EE);
        int4 d0 = dp[2 * i8], d1 = dp[2 * i8 + 1];
        dst[0] = d0.x; dst[1] = d0.y; dst[2] = d0.z; dst[3] = d0.w;
        dst[4] = d1.x; dst[5] = d1.y; dst[6] = d1.z; dst[7] = d1.w;
    } else {
        const longlong2* dp = (const longlong2*)((const long long*)ep + EE);
        #pragma unroll
        for (int q = 0; q < 4; q++) {
            longlong2 dd = dp[4 * i8 + q];
            dst[2 * q] = (int)dd.x; dst[2 * q + 1] = (int)dd.y;
        }
    }
    #pragma unroll
    for (int j = 0; j < 8; j++) {
        if ((dst[j] & 31) == 31) {
            long long idx = 8 * i8 + j;
            int g = dst[j] >> 5;
            int src = is32 ? ((const int*)ep)[idx]
                           : (int)((const long long*)ep)[idx];
            int pos = atomicAdd(&d_cnt[b][g], 1);
            if (pos < CAP) d_srcbuf[b][g * CAP + pos] = src;
        }
    }
}

// ---- fused tail: prep + edge softmax/aggregate + matvec + sigmoid + combine + mlp ----
// block = 8 warps over TGPB=16 graphs x 2 branches (4 tasks per warp)
// smem floats: shW[2][8192] | shB[2][128] | shMlp[128] | shRes[TGPB*2][128]
//              | shAtt[2][2][128] | shWvec[256]
#define SMF (2 * SS * HH + 2 * HH + HH + TGPB * 2 * HH + 4 * HH + 256)
#define SMB (SMF * 4)

extern __shared__ float smf[];

__global__ __launch_bounds__(256, 2)
void fused_tail_kernel(const float* __restrict__ up_x, const float* __restrict__ down_x,
                       const float* __restrict__ up_W, const float* __restrict__ up_b,
                       const float* __restrict__ down_W, const float* __restrict__ down_b,
                       const float* __restrict__ up_as, const float* __restrict__ up_ad,
                       const float* __restrict__ down_as, const float* __restrict__ down_ad,
                       const float* __restrict__ mlp_W, const float* __restrict__ mlp_b,
                       float* __restrict__ out) {
    float* shW    = smf;                        // [2][8192]
    float* shB    = smf + 2 * SS * HH;          // [2][128]
    float* shMlp  = shB + 2 * HH;               // [128]
    float* shRes  = shMlp + HH;                 // [TGPB*2][128]
    float* shAtt  = shRes + TGPB * 2 * HH;      // [2][2][128]  (b, src|dst)
    float* shWvec = shAtt + 4 * HH;             // [256] : b*128 + which*64 + s

    const int tid = threadIdx.x;
    const int gbase = blockIdx.x * TGPB;

    {   // stage both W matrices, biases, att vectors, mlp_W
        const float4* wu = (const float4*)up_W;
        const float4* wd = (const float4*)down_W;
        float4* s4 = (float4*)shW;
        #pragma unroll
        for (int i = tid; i < SS * HH / 4; i += 256) { s4[i] = wu[i]; s4[SS * HH / 4 + i] = wd[i]; }
    }
    if (tid < HH) {
        shB[tid]             = up_b[tid];
        shB[HH + tid]        = down_b[tid];
        shMlp[tid]           = mlp_W[tid];
        shAtt[tid]           = up_as[tid];
        shAtt[HH + tid]      = up_ad[tid];
        shAtt[2 * HH + tid]  = down_as[tid];
        shAtt[3 * HH + tid]  = down_ad[tid];
    }
    __syncthreads();

    // prep: shWvec[o] = dot(W_b[s,:], att_{b,which});  o = b*128 + which*64 + s
    {
        const int o = tid, pb = o >> 7, which = (o >> 6) & 1, s = o & 63;
        const float* Wrow = shW + pb * (SS * HH) + s * HH;
        const float* av   = shAtt + (pb * 2 + which) * HH;
        float acc = 0.f;
        #pragma unroll 8
        for (int jj = 0; jj < HH; jj++) {
            int j = (jj + s) & (HH - 1);        // skew: conflict-free banks
            acc += Wrow[j] * av[j];
        }
        shWvec[o] = acc;
    }
    __syncthreads();

    const int w    = tid >> 5;
    const int lane = tid & 31;
    const int b    = w & 1;
    const int l4   = 4 * lane;
    const float* xp = b ? down_x : up_x;
    const float* Wb = shW + b * (SS * HH);

    const float2 ws = *(const float2*)&shWvec[b * 128 + 2 * lane];
    const float2 wd = *(const float2*)&shWvec[b * 128 + 64 + 2 * lane];

    // prefetch all 4 task counters (independent loads), then reset them
    int cnt4[4];
    #pragma unroll
    for (int r = 0; r < 4; r++) {
        const int g = gbase + (w >> 1) + 4 * r;
        cnt4[r] = d_cnt[b][g];
    }
    if (lane == 0) {
        #pragma unroll
        for (int r = 0; r < 4; r++) d_cnt[b][gbase + (w >> 1) + 4 * r] = 0;
    }

    #pragma unroll
    for (int r = 0; r < 4; r++) {
        const int gl = (w >> 1) + 4 * r;      // 0..15
        const int g  = gbase + gl;
        const int self = g * 32 + 31;

        // a_dst
        float2 xs = *(const float2*)(xp + (size_t)self * SS + 2 * lane);
        float a_dst = xs.x * wd.x + xs.y * wd.y;
        #pragma unroll
        for (int o = 16; o; o >>= 1) a_dst += __shfl_xor_sync(FULL, a_dst, o);

        int cnt = cnt4[r];
        if (cnt > CAP) cnt = CAP;
        const int* srcs = &d_srcbuf[b][g * CAP];

        float m = -1e30f, ssum = 0.f, zx = 0.f, zy = 0.f;
        for (int t0 = 0; t0 < cnt; t0 += 8) {
            float2 xr[8];
            float  p[8];
            #pragma unroll
            for (int j = 0; j < 8; j++) {
                int t = t0 + j;
                int src = (t < cnt) ? srcs[t] : self;   // dummy rows get pw forced 0
                xr[j] = *(const float2*)(xp + (size_t)src * SS + 2 * lane);
                p[j] = xr[j].x * ws.x + xr[j].y * ws.y;
            }
            #pragma unroll
            for (int o = 16; o; o >>= 1) {
                #pragma unroll
                for (int j = 0; j < 8; j++) p[j] += __shfl_xor_sync(FULL, p[j], o);
            }
            float e[8], cm = -1e30f;
            #pragma unroll
            for (int j = 0; j < 8; j++) {
                float v = p[j] + a_dst;
                v = (v > 0.f) ? v : NEG * v;            // leaky_relu
                if (t0 + j >= cnt) v = -1e30f;
                e[j] = v;
                cm = fmaxf(cm, v);
            }
            float mn = fmaxf(m, cm);
            float sc = __expf(m - mn);
            ssum *= sc; zx *= sc; zy *= sc;
            #pragma unroll
            for (int j = 0; j < 8; j++) {
                float pw = __expf(e[j] - mn);
                ssum += pw;
                zx += pw * xr[j].x;
                zy += pw * xr[j].y;
            }
            m = mn;
        }
        const float inv = 1.f / (ssum + 1e-16f);
        zx *= inv; zy *= inv;

        // matvec: res = sigmoid(z @ W + bias)
        float a0 = 0.f, a1 = 0.f, a2 = 0.f, a3 = 0.f;
        #pragma unroll 8
        for (int k2 = 0; k2 < 32; k2++) {
            float z0 = __shfl_sync(FULL, zx, k2);
            float z1 = __shfl_sync(FULL, zy, k2);
            float4 wA = *(const float4*)(Wb + (2 * k2) * HH + l4);
            float4 wB = *(const float4*)(Wb + (2 * k2 + 1) * HH + l4);
            a0 += z0 * wA.x + z1 * wB.x;
            a1 += z0 * wA.y + z1 * wB.y;
            a2 += z0 * wA.z + z1 * wB.z;
            a3 += z0 * wA.w + z1 * wB.w;
        }
        const float* Bb = shB + b * HH;
        float4 sg;
        sg.x = 1.f / (1.f + __expf(-(a0 + Bb[l4])));
        sg.y = 1.f / (1.f + __expf(-(a1 + Bb[l4 + 1])));
        sg.z = 1.f / (1.f + __expf(-(a2 + Bb[l4 + 2])));
        sg.w = 1.f / (1.f + __expf(-(a3 + Bb[l4 + 3])));
        *(float4*)&shRes[(gl * 2 + b) * HH + l4] = sg;
    }
    __syncthreads();

    // combine: warp w handles graphs gbase+w and gbase+w+8
    #pragma unroll
    for (int r = 0; r < 2; r++) {
        const int gl = w + 8 * r;
        float4 u  = *(const float4*)&shRes[(gl * 2 + 0) * HH + l4];
        float4 d  = *(const float4*)&shRes[(gl * 2 + 1) * HH + l4];
        float4 mw = *(const float4*)&shMlp[l4];
        float p = u.x * d.x * mw.x + u.y * d.y * mw.y +
                  u.z * d.z * mw.z + u.w * d.w * mw.w;
        #pragma unroll
        for (int o = 16; o; o >>= 1) p += __shfl_xor_sync(FULL, p, o);
        if (lane == 0) out[gbase + gl] = p + mlp_b[0];
    }
}

extern "C" void kernel_launch(void* const* d_in, const int* in_sizes, int n_in,
                              void* d_out, int out_size) {
    const float* up_x    = (const float*)d_in[0];
    const void*  up_e    = d_in[1];
    const float* down_x  = (const float*)d_in[3];
    const void*  down_e  = d_in[4];
    const float* up_W    = (const float*)d_in[6];
    const float* up_as   = (const float*)d_in[7];
    const float* up_ad   = (const float*)d_in[8];
    const float* up_b    = (const float*)d_in[9];
    const float* down_W  = (const float*)d_in[10];
    const float* down_as = (const float*)d_in[11];
    const float* down_ad = (const float*)d_in[12];
    const float* down_b  = (const float*)d_in[13];
    const float* mlp_W   = (const float*)d_in[14];
    const float* mlp_b   = (const float*)d_in[15];
    float* out = (float*)d_out;

    cudaFuncSetAttribute(fused_tail_kernel,
                         cudaFuncAttributeMaxDynamicSharedMemorySize, SMB);

    filter_edges_kernel<<<2 * (EE / 8) / 256, 256>>>(up_e, down_e);
    fused_tail_kernel<<<GG / TGPB, 256, SMB>>>(up_x, down_x,
                                               up_W, up_b, down_W, down_b,
                                               up_as, up_ad, down_as, down_ad,
                                               mlp_W, mlp_b, out);
}